// round 10
// baseline (speedup 1.0000x reference)
#include <cuda_runtime.h>
#include <cuda_fp16.h>
#include <cstdint>

#define IN_F   4096
#define OUT_F  4096
#define MROWS  8192          // B*S = 4*2048

#define BM 256
#define BN 128
#define BK 64                // halves per k-tile
#define PITCH 72             // halves per smem row (144 B): ldmatrix conflict-free
#define STAGES 3
#define KTILES (IN_F / BK)   // 64
#define A_TILE_H (BM * PITCH)                     // 18432 halves
#define B_TILE_H (BN * PITCH)                     // 9216 halves
#define STAGE_H  (A_TILE_H + B_TILE_H)            // 27648 halves
#define SMEM_BYTES (STAGES * STAGE_H * 2)         // 165888

// ---------------- scratch (no runtime allocation allowed) -------------------
__device__ __align__(1024) __half g_w16[(size_t)OUT_F * IN_F];   // 32 MB
__device__ __align__(1024) __half g_x16[(size_t)MROWS * IN_F];   // 64 MB

// ---------------- helpers ----------------
__device__ __forceinline__ uint32_t s2u(const void* p) {
    uint32_t a;
    asm("{ .reg .u64 t; cvta.to.shared.u64 t, %1; cvt.u32.u64 %0, t; }" : "=r"(a) : "l"(p));
    return a;
}
__device__ __forceinline__ void cp_async16(uint32_t saddr, const void* gaddr) {
    asm volatile("cp.async.cg.shared.global [%0], [%1], 16;" :: "r"(saddr), "l"(gaddr) : "memory");
}
__device__ __forceinline__ void cp_commit() {
    asm volatile("cp.async.commit_group;" ::: "memory");
}
template <int N>
__device__ __forceinline__ void cp_wait() {
    asm volatile("cp.async.wait_group %0;" :: "n"(N) : "memory");
}
__device__ __forceinline__ void ldsm_x4(uint32_t* r, uint32_t addr) {
    asm volatile("ldmatrix.sync.aligned.m8n8.x4.shared.b16 {%0,%1,%2,%3}, [%4];"
                 : "=r"(r[0]), "=r"(r[1]), "=r"(r[2]), "=r"(r[3]) : "r"(addr));
}
__device__ __forceinline__ void mma_f16(float* d, const uint32_t* a, const uint32_t* b) {
    asm volatile(
        "mma.sync.aligned.m16n8k16.row.col.f32.f16.f16.f32 "
        "{%0,%1,%2,%3}, {%4,%5,%6,%7}, {%8,%9}, {%0,%1,%2,%3};"
        : "+f"(d[0]), "+f"(d[1]), "+f"(d[2]), "+f"(d[3])
        : "r"(a[0]), "r"(a[1]), "r"(a[2]), "r"(a[3]), "r"(b[0]), "r"(b[1]));
}

// ---------------- kernel 1: dequantize W -> fp16 ----------------------------
__global__ void __launch_bounds__(256) wdeq_kernel(const float* __restrict__ cent,
                                                   const int* __restrict__ idx,
                                                   __half* __restrict__ w) {
    __shared__ __half c[256];
    int t = threadIdx.x;
    c[t] = __float2half_rn(cent[t]);
    __syncthreads();
    size_t i = ((size_t)blockIdx.x * 256 + t) * 8;
    int4 v0 = *reinterpret_cast<const int4*>(idx + i);
    int4 v1 = *reinterpret_cast<const int4*>(idx + i + 4);
    __half h[8];
    h[0] = c[v0.x]; h[1] = c[v0.y]; h[2] = c[v0.z]; h[3] = c[v0.w];
    h[4] = c[v1.x]; h[5] = c[v1.y]; h[6] = c[v1.z]; h[7] = c[v1.w];
    *reinterpret_cast<uint4*>(w + i) = *reinterpret_cast<uint4*>(h);
}

// ---------------- kernel 2: X fp32 -> fp16 ----------------------------------
__global__ void __launch_bounds__(256) xcvt_kernel(const float* __restrict__ x,
                                                   __half* __restrict__ y) {
    size_t i = ((size_t)blockIdx.x * 256 + threadIdx.x) * 8;
    float4 v0 = *reinterpret_cast<const float4*>(x + i);
    float4 v1 = *reinterpret_cast<const float4*>(x + i + 4);
    __half h[8];
    h[0] = __float2half_rn(v0.x); h[1] = __float2half_rn(v0.y);
    h[2] = __float2half_rn(v0.z); h[3] = __float2half_rn(v0.w);
    h[4] = __float2half_rn(v1.x); h[5] = __float2half_rn(v1.y);
    h[6] = __float2half_rn(v1.z); h[7] = __float2half_rn(v1.w);
    *reinterpret_cast<uint4*>(y + i) = *reinterpret_cast<uint4*>(h);
}

// ---------------- kernel 3: fp16 mma GEMM, 256x128 CTA, 16 warps x (64x32) --
// out[m,n] = sum_k X[m,k] * W[n,k]
__global__ void __launch_bounds__(512, 1)
gemm_f16(const __half* __restrict__ X, const __half* __restrict__ W,
         float* __restrict__ out) {
    extern __shared__ __half smem[];
    __half* As = smem;                             // [STAGES][BM][PITCH]
    __half* Bs = smem + STAGES * A_TILE_H;         // [STAGES][BN][PITCH]
    const uint32_t As_u = s2u(As);
    const uint32_t Bs_u = s2u(Bs);

    const int tid = threadIdx.x;
    const int wid = tid >> 5, lane = tid & 31;
    const int warp_m = wid >> 2;      // 0..3 -> 64 rows each
    const int warp_n = wid & 3;       // 0..3 -> 32 cols each

    // grid swizzle: 4 M-tiles per supertile column (L2 reuse of W)
    const int NT = OUT_F / BN;        // 32
    const int GM = 4;
    int bid = blockIdx.x;
    int grp = bid / (GM * NT);
    int inb = bid % (GM * NT);
    int m_tile = grp * GM + (inb % GM);
    int n_tile = inb / GM;
    const int m_base = m_tile * BM;
    const int n_base = n_tile * BN;

    // gmem->smem: 512 thr, 64 rows x 8 chunks(16B) per iter
    const int ld_row0 = tid >> 3;            // 0..63
    const int ld_ch   = (tid & 7) * 8;       // halves

    // ldmatrix lane address components (in halves)
    const int l7 = lane & 7;
    const int a_row = warp_m * 64 + l7 + ((lane >> 3) & 1) * 8;
    const int a_kh  = ((lane >> 4) & 1) * 8;
    const int b_row = warp_n * 32 + l7 + ((lane >> 4) & 1) * 8;
    const int b_kh  = ((lane >> 3) & 1) * 8;
    const uint32_t a_base = As_u + (uint32_t)(a_row * PITCH + a_kh) * 2;
    const uint32_t b_base = Bs_u + (uint32_t)(b_row * PITCH + b_kh) * 2;

    float acc[4][4][4];
    #pragma unroll
    for (int mi = 0; mi < 4; mi++)
        #pragma unroll
        for (int ni = 0; ni < 4; ni++)
            #pragma unroll
            for (int e = 0; e < 4; e++) acc[mi][ni][e] = 0.f;

    auto load_tile = [&](int kt, int s) {
        const __half* ga = X + (size_t)(m_base + ld_row0) * IN_F + kt * BK + ld_ch;
        uint32_t sa = As_u + (uint32_t)(s * A_TILE_H + ld_row0 * PITCH + ld_ch) * 2;
        #pragma unroll
        for (int i = 0; i < 4; i++) {          // 4 x 64 rows = 256 (A)
            cp_async16(sa, ga);
            ga += 64 * IN_F;
            sa += 64 * PITCH * 2;
        }
        const __half* gb = W + (size_t)(n_base + ld_row0) * IN_F + kt * BK + ld_ch;
        uint32_t sb = Bs_u + (uint32_t)(s * B_TILE_H + ld_row0 * PITCH + ld_ch) * 2;
        #pragma unroll
        for (int i = 0; i < 2; i++) {          // 2 x 64 rows = 128 (B)
            cp_async16(sb, gb);
            gb += 64 * IN_F;
            sb += 64 * PITCH * 2;
        }
        cp_commit();
    };

    load_tile(0, 0);
    load_tile(1, 1);

    int sc = 0;
    for (int kt = 0; kt < KTILES; kt++) {
        if (kt + 1 < KTILES) cp_wait<1>(); else cp_wait<0>();
        __syncthreads();
        if (kt + 2 < KTILES) {
            int sl = sc + 2; if (sl >= STAGES) sl -= STAGES;
            load_tile(kt + 2, sl);
        }

        const uint32_t a_off = (uint32_t)(sc * A_TILE_H * 2);
        const uint32_t b_off = (uint32_t)(sc * B_TILE_H * 2);
        #pragma unroll
        for (int k0 = 0; k0 < BK; k0 += 16) {
            uint32_t a[4][4], b[2][4];
            #pragma unroll
            for (int mi = 0; mi < 4; mi++)
                ldsm_x4(a[mi], a_base + a_off + (uint32_t)(k0 + mi * 16 * PITCH) * 2);
            ldsm_x4(b[0], b_base + b_off + (uint32_t)(k0) * 2);
            ldsm_x4(b[1], b_base + b_off + (uint32_t)(k0 + 16 * PITCH) * 2);
            #pragma unroll
            for (int mi = 0; mi < 4; mi++) {
                mma_f16(acc[mi][0], a[mi], &b[0][0]);
                mma_f16(acc[mi][1], a[mi], &b[0][2]);
                mma_f16(acc[mi][2], a[mi], &b[1][0]);
                mma_f16(acc[mi][3], a[mi], &b[1][2]);
            }
        }
        sc = (sc + 1 == STAGES) ? 0 : sc + 1;
    }

    // epilogue: direct STG.64
    #pragma unroll
    for (int mi = 0; mi < 4; mi++) {
        int r0 = m_base + warp_m * 64 + mi * 16 + (lane >> 2);
        #pragma unroll
        for (int ni = 0; ni < 4; ni++) {
            int c = n_base + warp_n * 32 + ni * 8 + 2 * (lane & 3);
            float2 v0 = make_float2(acc[mi][ni][0], acc[mi][ni][1]);
            float2 v1 = make_float2(acc[mi][ni][2], acc[mi][ni][3]);
            *reinterpret_cast<float2*>(out + (size_t)r0 * OUT_F + c) = v0;
            *reinterpret_cast<float2*>(out + (size_t)(r0 + 8) * OUT_F + c) = v1;
        }
    }
}

// ---------------- host ----------------
extern "C" void kernel_launch(void* const* d_in, const int* in_sizes, int n_in,
                              void* d_out, int out_size) {
    const float* x    = (const float*)d_in[0];   // [8192, 4096] fp32
    const float* cent = (const float*)d_in[1];   // [256, 1] fp32
    const int*   idx  = (const int*)d_in[2];     // [4096, 4096] int32
    float* out = (float*)d_out;                  // [8192, 4096] fp32

    void* w16_ptr = nullptr; cudaGetSymbolAddress(&w16_ptr, g_w16);
    void* x16_ptr = nullptr; cudaGetSymbolAddress(&x16_ptr, g_x16);

    wdeq_kernel<<<(size_t)OUT_F * IN_F / 2048, 256>>>(cent, idx, (__half*)w16_ptr);
    xcvt_kernel<<<(size_t)MROWS * IN_F / 2048, 256>>>(x, (__half*)x16_ptr);

    cudaFuncSetAttribute(gemm_f16, cudaFuncAttributeMaxDynamicSharedMemorySize, SMEM_BYTES);
    int grid = (MROWS / BM) * (OUT_F / BN);   // 32 * 32 = 1024
    gemm_f16<<<grid, 512, SMEM_BYTES>>>((const __half*)x16_ptr, (const __half*)w16_ptr, out);
}

// round 11
// speedup vs baseline: 1.2128x; 1.2128x over previous
#include <cuda_runtime.h>
#include <cuda_fp16.h>
#include <cstdint>

#define IN_F   4096
#define OUT_F  4096
#define MROWS  8192          // B*S = 4*2048

#define BM 128
#define BN 128
#define BK 64                // halves per k-tile
#define PITCH 72             // halves per smem row (144 B): ldmatrix conflict-free
#define STAGES 3
#define KTILES (IN_F / BK)   // 64
#define TILE_H (BM * PITCH)                        // 9216 halves per matrix per stage
#define SMEM_HDR 1024                              // mbarriers live here
#define SMEM_BYTES (SMEM_HDR + 2 * STAGES * TILE_H * 2)   // 111616

// mbarrier byte offsets within the header (relative to dynamic smem base)
#define MB_FULL(s)  ((s) * 16)
#define MB_EMPTY(s) ((s) * 16 + 8)

// ---------------- scratch (no runtime allocation allowed) -------------------
__device__ __align__(1024) __half g_w16[(size_t)OUT_F * IN_F];   // 32 MB
__device__ __align__(1024) __half g_x16[(size_t)MROWS * IN_F];   // 64 MB

// ---------------- helpers ----------------
__device__ __forceinline__ uint32_t s2u(const void* p) {
    uint32_t a;
    asm("{ .reg .u64 t; cvta.to.shared.u64 t, %1; cvt.u32.u64 %0, t; }" : "=r"(a) : "l"(p));
    return a;
}
__device__ __forceinline__ void cp_async16(uint32_t saddr, const void* gaddr) {
    asm volatile("cp.async.cg.shared.global [%0], [%1], 16;" :: "r"(saddr), "l"(gaddr) : "memory");
}
__device__ __forceinline__ void mbar_init(uint32_t m, uint32_t cnt) {
    asm volatile("mbarrier.init.shared.b64 [%0], %1;" :: "r"(m), "r"(cnt) : "memory");
}
__device__ __forceinline__ void mbar_arrive(uint32_t m) {
    asm volatile("{ .reg .b64 t; mbarrier.arrive.shared.b64 t, [%0]; }" :: "r"(m) : "memory");
}
__device__ __forceinline__ void cp_async_mbar_arrive(uint32_t m) {
    asm volatile("cp.async.mbarrier.arrive.noinc.shared.b64 [%0];" :: "r"(m) : "memory");
}
__device__ __forceinline__ void mbar_wait(uint32_t m, uint32_t parity) {
    asm volatile(
        "{\n\t.reg .pred P;\n\t"
        "WL_%=:\n\t"
        "mbarrier.try_wait.parity.acquire.cta.shared::cta.b64 P, [%0], %1, 0x989680;\n\t"
        "@P bra.uni WD_%=;\n\t"
        "bra.uni WL_%=;\n\t"
        "WD_%=:\n\t}"
        :: "r"(m), "r"(parity) : "memory");
}
__device__ __forceinline__ void ldsm_x4(uint32_t* r, uint32_t addr) {
    asm volatile("ldmatrix.sync.aligned.m8n8.x4.shared.b16 {%0,%1,%2,%3}, [%4];"
                 : "=r"(r[0]), "=r"(r[1]), "=r"(r[2]), "=r"(r[3]) : "r"(addr));
}
__device__ __forceinline__ void mma_f16(float* d, const uint32_t* a, const uint32_t* b) {
    asm volatile(
        "mma.sync.aligned.m16n8k16.row.col.f32.f16.f16.f32 "
        "{%0,%1,%2,%3}, {%4,%5,%6,%7}, {%8,%9}, {%0,%1,%2,%3};"
        : "+f"(d[0]), "+f"(d[1]), "+f"(d[2]), "+f"(d[3])
        : "r"(a[0]), "r"(a[1]), "r"(a[2]), "r"(a[3]), "r"(b[0]), "r"(b[1]));
}

// ---------------- kernel 1: dequantize W -> fp16 (bank-pinned table) --------
__global__ void __launch_bounds__(256) wdeq_kernel(const float* __restrict__ cent,
                                                   const int* __restrict__ idx,
                                                   __half* __restrict__ w) {
    // 32-way replicated table: word index = entry*32 + lane -> bank == lane
    __shared__ uint32_t tab[256 * 32];   // 32 KB
    int t = threadIdx.x;
    #pragma unroll
    for (int i = 0; i < 32; i++) {
        int word = t + i * 256;
        int e = word >> 5;
        tab[word] = (uint32_t)__half_as_ushort(__float2half_rn(cent[e]));
    }
    __syncthreads();
    const int lane = t & 31;
    size_t i = ((size_t)blockIdx.x * 256 + t) * 8;
    int4 v0 = *reinterpret_cast<const int4*>(idx + i);
    int4 v1 = *reinterpret_cast<const int4*>(idx + i + 4);
    __half h[8];
    h[0] = __ushort_as_half((unsigned short)tab[v0.x * 32 + lane]);
    h[1] = __ushort_as_half((unsigned short)tab[v0.y * 32 + lane]);
    h[2] = __ushort_as_half((unsigned short)tab[v0.z * 32 + lane]);
    h[3] = __ushort_as_half((unsigned short)tab[v0.w * 32 + lane]);
    h[4] = __ushort_as_half((unsigned short)tab[v1.x * 32 + lane]);
    h[5] = __ushort_as_half((unsigned short)tab[v1.y * 32 + lane]);
    h[6] = __ushort_as_half((unsigned short)tab[v1.z * 32 + lane]);
    h[7] = __ushort_as_half((unsigned short)tab[v1.w * 32 + lane]);
    *reinterpret_cast<uint4*>(w + i) = *reinterpret_cast<uint4*>(h);
}

// ---------------- kernel 2: X fp32 -> fp16 ----------------------------------
__global__ void __launch_bounds__(256) xcvt_kernel(const float* __restrict__ x,
                                                   __half* __restrict__ y) {
    size_t i = ((size_t)blockIdx.x * 256 + threadIdx.x) * 8;
    float4 v0 = *reinterpret_cast<const float4*>(x + i);
    float4 v1 = *reinterpret_cast<const float4*>(x + i + 4);
    __half h[8];
    h[0] = __float2half_rn(v0.x); h[1] = __float2half_rn(v0.y);
    h[2] = __float2half_rn(v0.z); h[3] = __float2half_rn(v0.w);
    h[4] = __float2half_rn(v1.x); h[5] = __float2half_rn(v1.y);
    h[6] = __float2half_rn(v1.z); h[7] = __float2half_rn(v1.w);
    *reinterpret_cast<uint4*>(y + i) = *reinterpret_cast<uint4*>(h);
}

// ---------------- kernel 3: fp16 mma GEMM, mbarrier-staged pipeline ---------
// out[m,n] = sum_k X[m,k] * W[n,k]
__global__ void __launch_bounds__(256, 2)
gemm_f16(const __half* __restrict__ X, const __half* __restrict__ W,
         float* __restrict__ out) {
    extern __shared__ char smem_raw[];
    const uint32_t sb = s2u(smem_raw);                 // mbarriers at sb
    __half* As = reinterpret_cast<__half*>(smem_raw + SMEM_HDR);
    __half* Bs = As + STAGES * TILE_H;
    const uint32_t As_u = sb + SMEM_HDR;
    const uint32_t Bs_u = As_u + STAGES * TILE_H * 2;

    const int tid = threadIdx.x;
    const int wid = tid >> 5, lane = tid & 31;
    const int warp_m = wid >> 2;      // 0..1 -> 64 rows
    const int warp_n = wid & 3;       // 0..3 -> 32 cols

    // init mbarriers: full/empty expect 256 arrivals each phase
    if (tid == 0) {
        #pragma unroll
        for (int s = 0; s < STAGES; s++) {
            mbar_init(sb + MB_FULL(s), 256);
            mbar_init(sb + MB_EMPTY(s), 256);
        }
    }
    __syncthreads();

    // grid swizzle: 8 M-tiles per supertile column (L2 reuse of W)
    const int NT = OUT_F / BN;        // 32
    const int GM = 8;
    int bid = blockIdx.x;
    int grp = bid / (GM * NT);
    int inb = bid % (GM * NT);
    int m_tile = grp * GM + (inb % GM);
    int n_tile = inb / GM;
    const int m_base = m_tile * BM;
    const int n_base = n_tile * BN;

    // gmem->smem: 128 rows x 8 chunks(16B); 256 thr x 4 iters
    const int ld_row0 = tid >> 3;            // +32/iter
    const int ld_ch   = (tid & 7) * 8;       // halves

    // ldmatrix lane address components (in halves)
    const int l7 = lane & 7;
    const int a_row = warp_m * 64 + l7 + ((lane >> 3) & 1) * 8;
    const int a_kh  = ((lane >> 4) & 1) * 8;
    const int b_row = warp_n * 32 + l7 + ((lane >> 4) & 1) * 8;
    const int b_kh  = ((lane >> 3) & 1) * 8;
    const uint32_t a_base = As_u + (uint32_t)(a_row * PITCH + a_kh) * 2;
    const uint32_t b_base = Bs_u + (uint32_t)(b_row * PITCH + b_kh) * 2;

    float acc[4][4][4];
    #pragma unroll
    for (int mi = 0; mi < 4; mi++)
        #pragma unroll
        for (int ni = 0; ni < 4; ni++)
            #pragma unroll
            for (int e = 0; e < 4; e++) acc[mi][ni][e] = 0.f;

    auto load_tile = [&](int kt, int s) {
        const __half* ga = X + (size_t)(m_base + ld_row0) * IN_F + kt * BK + ld_ch;
        const __half* gb = W + (size_t)(n_base + ld_row0) * IN_F + kt * BK + ld_ch;
        uint32_t sa = As_u + (uint32_t)(s * TILE_H + ld_row0 * PITCH + ld_ch) * 2;
        uint32_t sb2 = Bs_u + (uint32_t)(s * TILE_H + ld_row0 * PITCH + ld_ch) * 2;
        #pragma unroll
        for (int i = 0; i < 4; i++) {
            cp_async16(sa, ga);
            cp_async16(sb2, gb);
            ga += 32 * IN_F;       gb += 32 * IN_F;
            sa += 32 * PITCH * 2;  sb2 += 32 * PITCH * 2;
        }
    };

    // ---- prologue: fill stages 0 and 1 (empty waits pass: producer phase 1)
    mbar_wait(sb + MB_EMPTY(0), 1);
    load_tile(0, 0);
    cp_async_mbar_arrive(sb + MB_FULL(0));
    mbar_wait(sb + MB_EMPTY(1), 1);
    load_tile(1, 1);
    cp_async_mbar_arrive(sb + MB_FULL(1));

    int ps = 2, pph = 1;      // producer empty-cursor (next stage to fill)
    int cs = 0, cph = 0;      // consumer full-cursor

    for (int kt = 0; kt < KTILES; kt++) {
        if (kt + 2 < KTILES) {
            mbar_wait(sb + MB_EMPTY(ps), pph);
            load_tile(kt + 2, ps);
            cp_async_mbar_arrive(sb + MB_FULL(ps));
            if (++ps == STAGES) { ps = 0; pph ^= 1; }
        }

        mbar_wait(sb + MB_FULL(cs), cph);

        const uint32_t st_off = (uint32_t)(cs * TILE_H * 2);
        #pragma unroll
        for (int k0 = 0; k0 < BK; k0 += 16) {
            uint32_t a[4][4], b[2][4];
            #pragma unroll
            for (int mi = 0; mi < 4; mi++)
                ldsm_x4(a[mi], a_base + st_off + (uint32_t)(k0 + mi * 16 * PITCH) * 2);
            ldsm_x4(b[0], b_base + st_off + (uint32_t)(k0) * 2);
            ldsm_x4(b[1], b_base + st_off + (uint32_t)(k0 + 16 * PITCH) * 2);
            #pragma unroll
            for (int mi = 0; mi < 4; mi++) {
                mma_f16(acc[mi][0], a[mi], &b[0][0]);
                mma_f16(acc[mi][1], a[mi], &b[0][2]);
                mma_f16(acc[mi][2], a[mi], &b[1][0]);
                mma_f16(acc[mi][3], a[mi], &b[1][2]);
            }
        }

        mbar_arrive(sb + MB_EMPTY(cs));
        if (++cs == STAGES) { cs = 0; cph ^= 1; }
    }

    // epilogue: direct STG.64 (accumulators in regs; no smem dependence)
    #pragma unroll
    for (int mi = 0; mi < 4; mi++) {
        int r0 = m_base + warp_m * 64 + mi * 16 + (lane >> 2);
        #pragma unroll
        for (int ni = 0; ni < 4; ni++) {
            int c = n_base + warp_n * 32 + ni * 8 + 2 * (lane & 3);
            float2 v0 = make_float2(acc[mi][ni][0], acc[mi][ni][1]);
            float2 v1 = make_float2(acc[mi][ni][2], acc[mi][ni][3]);
            *reinterpret_cast<float2*>(out + (size_t)r0 * OUT_F + c) = v0;
            *reinterpret_cast<float2*>(out + (size_t)(r0 + 8) * OUT_F + c) = v1;
        }
    }
}

// ---------------- host ----------------
extern "C" void kernel_launch(void* const* d_in, const int* in_sizes, int n_in,
                              void* d_out, int out_size) {
    const float* x    = (const float*)d_in[0];   // [8192, 4096] fp32
    const float* cent = (const float*)d_in[1];   // [256, 1] fp32
    const int*   idx  = (const int*)d_in[2];     // [4096, 4096] int32
    float* out = (float*)d_out;                  // [8192, 4096] fp32

    void* w16_ptr = nullptr; cudaGetSymbolAddress(&w16_ptr, g_w16);
    void* x16_ptr = nullptr; cudaGetSymbolAddress(&x16_ptr, g_x16);

    wdeq_kernel<<<(size_t)OUT_F * IN_F / 2048, 256>>>(cent, idx, (__half*)w16_ptr);
    xcvt_kernel<<<(size_t)MROWS * IN_F / 2048, 256>>>(x, (__half*)x16_ptr);

    cudaFuncSetAttribute(gemm_f16, cudaFuncAttributeMaxDynamicSharedMemorySize, SMEM_BYTES);
    int grid = (MROWS / BM) * (OUT_F / BN);   // 64 * 32 = 2048
    gemm_f16<<<grid, 256, SMEM_BYTES>>>((const __half*)x16_ptr, (const __half*)w16_ptr, out);
}

// round 12
// speedup vs baseline: 1.2382x; 1.0210x over previous
#include <cuda_runtime.h>
#include <cuda_fp16.h>
#include <cstdint>

#define IN_F   4096
#define OUT_F  4096
#define MROWS  8192          // B*S = 4*2048

#define BM 128
#define BN 128
#define BK 64                // halves per k-tile
#define PITCH 72             // halves per smem row (144 B): ldmatrix conflict-free
#define STAGES 3
#define KTILES (IN_F / BK)   // 64
#define TILE_H (BM * PITCH)                        // 9216 halves per matrix per stage
#define SMEM_HDR 1024                              // mbarriers live here
#define SMEM_BYTES (SMEM_HDR + 2 * STAGES * TILE_H * 2)   // 111616

#define MB_FULL(s)  ((s) * 16)
#define MB_EMPTY(s) ((s) * 16 + 8)

// ---------------- scratch (no runtime allocation allowed) -------------------
__device__ __align__(1024) __half g_w16[(size_t)OUT_F * IN_F];   // 32 MB
__device__ __align__(1024) __half g_x16[(size_t)MROWS * IN_F];   // 64 MB

// ---------------- helpers ----------------
__device__ __forceinline__ uint32_t s2u(const void* p) {
    uint32_t a;
    asm("{ .reg .u64 t; cvta.to.shared.u64 t, %1; cvt.u32.u64 %0, t; }" : "=r"(a) : "l"(p));
    return a;
}
__device__ __forceinline__ void cp_async16(uint32_t saddr, const void* gaddr) {
    asm volatile("cp.async.cg.shared.global [%0], [%1], 16;" :: "r"(saddr), "l"(gaddr) : "memory");
}
__device__ __forceinline__ void mbar_init(uint32_t m, uint32_t cnt) {
    asm volatile("mbarrier.init.shared.b64 [%0], %1;" :: "r"(m), "r"(cnt) : "memory");
}
__device__ __forceinline__ void mbar_arrive(uint32_t m) {
    asm volatile("{ .reg .b64 t; mbarrier.arrive.shared.b64 t, [%0]; }" :: "r"(m) : "memory");
}
__device__ __forceinline__ void cp_async_mbar_arrive(uint32_t m) {
    asm volatile("cp.async.mbarrier.arrive.noinc.shared.b64 [%0];" :: "r"(m) : "memory");
}
__device__ __forceinline__ void mbar_wait(uint32_t m, uint32_t parity) {
    asm volatile(
        "{\n\t.reg .pred P;\n\t"
        "WL_%=:\n\t"
        "mbarrier.try_wait.parity.acquire.cta.shared::cta.b64 P, [%0], %1, 0x989680;\n\t"
        "@P bra.uni WD_%=;\n\t"
        "bra.uni WL_%=;\n\t"
        "WD_%=:\n\t}"
        :: "r"(m), "r"(parity) : "memory");
}
__device__ __forceinline__ void ldsm_x4(uint32_t* r, uint32_t addr) {
    asm volatile("ldmatrix.sync.aligned.m8n8.x4.shared.b16 {%0,%1,%2,%3}, [%4];"
                 : "=r"(r[0]), "=r"(r[1]), "=r"(r[2]), "=r"(r[3]) : "r"(addr));
}
__device__ __forceinline__ void mma_f16(float* d, const uint32_t* a, const uint32_t* b) {
    asm volatile(
        "mma.sync.aligned.m16n8k16.row.col.f32.f16.f16.f32 "
        "{%0,%1,%2,%3}, {%4,%5,%6,%7}, {%8,%9}, {%0,%1,%2,%3};"
        : "+f"(d[0]), "+f"(d[1]), "+f"(d[2]), "+f"(d[3])
        : "r"(a[0]), "r"(a[1]), "r"(a[2]), "r"(a[3]), "r"(b[0]), "r"(b[1]));
}

// ------------- kernel 1: fused preprocessing (wdeq || xcvt) -----------------
// blocks [0, NB_W): dequantize W -> fp16 ; blocks [NB_W, NB_W+NB_X): X -> fp16
#define NB_W ((size_t)OUT_F * IN_F / 2048)   // 8192
#define NB_X ((size_t)MROWS * IN_F / 2048)   // 16384

__global__ void __launch_bounds__(256) prep_kernel(const float* __restrict__ cent,
                                                   const int* __restrict__ idx,
                                                   const float* __restrict__ x,
                                                   __half* __restrict__ w,
                                                   __half* __restrict__ y) {
    int t = threadIdx.x;
    if (blockIdx.x < NB_W) {
        __shared__ __half c[256];
        c[t] = __float2half_rn(cent[t]);
        __syncthreads();
        size_t i = ((size_t)blockIdx.x * 256 + t) * 8;
        int4 v0 = *reinterpret_cast<const int4*>(idx + i);
        int4 v1 = *reinterpret_cast<const int4*>(idx + i + 4);
        __half h[8];
        h[0] = c[v0.x]; h[1] = c[v0.y]; h[2] = c[v0.z]; h[3] = c[v0.w];
        h[4] = c[v1.x]; h[5] = c[v1.y]; h[6] = c[v1.z]; h[7] = c[v1.w];
        *reinterpret_cast<uint4*>(w + i) = *reinterpret_cast<uint4*>(h);
    } else {
        size_t i = ((size_t)(blockIdx.x - NB_W) * 256 + t) * 8;
        float4 v0 = *reinterpret_cast<const float4*>(x + i);
        float4 v1 = *reinterpret_cast<const float4*>(x + i + 4);
        __half h[8];
        h[0] = __float2half_rn(v0.x); h[1] = __float2half_rn(v0.y);
        h[2] = __float2half_rn(v0.z); h[3] = __float2half_rn(v0.w);
        h[4] = __float2half_rn(v1.x); h[5] = __float2half_rn(v1.y);
        h[6] = __float2half_rn(v1.z); h[7] = __float2half_rn(v1.w);
        *reinterpret_cast<uint4*>(y + i) = *reinterpret_cast<uint4*>(h);
    }
}

// ---------------- kernel 2: fp16 mma GEMM, mbarrier-staged pipeline ---------
// out[m,n] = sum_k X[m,k] * W[n,k]
__global__ void __launch_bounds__(256, 2)
gemm_f16(const __half* __restrict__ X, const __half* __restrict__ W,
         float* __restrict__ out) {
    extern __shared__ char smem_raw[];
    const uint32_t sb = s2u(smem_raw);                 // mbarriers at sb
    const uint32_t As_u = sb + SMEM_HDR;
    const uint32_t Bs_u = As_u + STAGES * TILE_H * 2;

    const int tid = threadIdx.x;
    const int wid = tid >> 5, lane = tid & 31;
    const int warp_m = wid >> 2;      // 0..1 -> 64 rows
    const int warp_n = wid & 3;       // 0..3 -> 32 cols

    if (tid == 0) {
        #pragma unroll
        for (int s = 0; s < STAGES; s++) {
            mbar_init(sb + MB_FULL(s), 256);
            mbar_init(sb + MB_EMPTY(s), 256);
        }
    }
    __syncthreads();

    // grid swizzle: 8 M-tiles per supertile column (L2 reuse of W)
    const int NT = OUT_F / BN;        // 32
    const int GM = 8;
    int bid = blockIdx.x;
    int grp = bid / (GM * NT);
    int inb = bid % (GM * NT);
    int m_tile = grp * GM + (inb % GM);
    int n_tile = inb / GM;
    const int m_base = m_tile * BM;
    const int n_base = n_tile * BN;

    // gmem->smem: 128 rows x 8 chunks(16B); 256 thr x 4 iters
    const int ld_row0 = tid >> 3;            // +32/iter
    const int ld_ch   = (tid & 7) * 8;       // halves

    // ldmatrix lane address components (in halves)
    const int l7 = lane & 7;
    const int a_row = warp_m * 64 + l7 + ((lane >> 3) & 1) * 8;
    const int a_kh  = ((lane >> 4) & 1) * 8;
    const int b_row = warp_n * 32 + l7 + ((lane >> 4) & 1) * 8;
    const int b_kh  = ((lane >> 3) & 1) * 8;
    const uint32_t a_base = As_u + (uint32_t)(a_row * PITCH + a_kh) * 2;
    const uint32_t b_base = Bs_u + (uint32_t)(b_row * PITCH + b_kh) * 2;

    float acc[4][4][4];
    #pragma unroll
    for (int mi = 0; mi < 4; mi++)
        #pragma unroll
        for (int ni = 0; ni < 4; ni++)
            #pragma unroll
            for (int e = 0; e < 4; e++) acc[mi][ni][e] = 0.f;

    auto load_tile = [&](int kt, int s) {
        const __half* ga = X + (size_t)(m_base + ld_row0) * IN_F + kt * BK + ld_ch;
        const __half* gb = W + (size_t)(n_base + ld_row0) * IN_F + kt * BK + ld_ch;
        uint32_t sa = As_u + (uint32_t)(s * TILE_H + ld_row0 * PITCH + ld_ch) * 2;
        uint32_t sb2 = Bs_u + (uint32_t)(s * TILE_H + ld_row0 * PITCH + ld_ch) * 2;
        #pragma unroll
        for (int i = 0; i < 4; i++) {
            cp_async16(sa, ga);
            cp_async16(sb2, gb);
            ga += 32 * IN_F;       gb += 32 * IN_F;
            sa += 32 * PITCH * 2;  sb2 += 32 * PITCH * 2;
        }
    };

    auto ldfrags = [&](uint32_t st_off, int k0, uint32_t (&a)[4][4], uint32_t (&b)[2][4]) {
        #pragma unroll
        for (int mi = 0; mi < 4; mi++)
            ldsm_x4(a[mi], a_base + st_off + (uint32_t)(k0 + mi * 16 * PITCH) * 2);
        ldsm_x4(b[0], b_base + st_off + (uint32_t)(k0) * 2);
        ldsm_x4(b[1], b_base + st_off + (uint32_t)(k0 + 16 * PITCH) * 2);
    };

    auto do_mmas = [&](uint32_t (&a)[4][4], uint32_t (&b)[2][4]) {
        #pragma unroll
        for (int mi = 0; mi < 4; mi++) {
            mma_f16(acc[mi][0], a[mi], &b[0][0]);
            mma_f16(acc[mi][1], a[mi], &b[0][2]);
            mma_f16(acc[mi][2], a[mi], &b[1][0]);
            mma_f16(acc[mi][3], a[mi], &b[1][2]);
        }
    };

    // ---- prologue: fill stages 0 and 1 (empty waits pass: producer phase 1)
    mbar_wait(sb + MB_EMPTY(0), 1);
    load_tile(0, 0);
    cp_async_mbar_arrive(sb + MB_FULL(0));
    mbar_wait(sb + MB_EMPTY(1), 1);
    load_tile(1, 1);
    cp_async_mbar_arrive(sb + MB_FULL(1));

    int ps = 2, pph = 1;      // producer empty-cursor
    int cs = 0, cph = 0;      // consumer full-cursor

    for (int kt = 0; kt < KTILES; kt++) {
        if (kt + 2 < KTILES) {
            mbar_wait(sb + MB_EMPTY(ps), pph);
            load_tile(kt + 2, ps);
            cp_async_mbar_arrive(sb + MB_FULL(ps));
            if (++ps == STAGES) { ps = 0; pph ^= 1; }
        }

        mbar_wait(sb + MB_FULL(cs), cph);

        const uint32_t st_off = (uint32_t)(cs * TILE_H * 2);
        uint32_t a[4][4], b[2][4];
        #pragma unroll
        for (int ks = 0; ks < 3; ks++) {
            ldfrags(st_off, ks * 16, a, b);
            do_mmas(a, b);
        }
        // last k-step peeled: release the stage as soon as fragments are out
        ldfrags(st_off, 48, a, b);
        mbar_arrive(sb + MB_EMPTY(cs));
        do_mmas(a, b);

        if (++cs == STAGES) { cs = 0; cph ^= 1; }
    }

    // epilogue: direct STG.64
    #pragma unroll
    for (int mi = 0; mi < 4; mi++) {
        int r0 = m_base + warp_m * 64 + mi * 16 + (lane >> 2);
        #pragma unroll
        for (int ni = 0; ni < 4; ni++) {
            int c = n_base + warp_n * 32 + ni * 8 + 2 * (lane & 3);
            float2 v0 = make_float2(acc[mi][ni][0], acc[mi][ni][1]);
            float2 v1 = make_float2(acc[mi][ni][2], acc[mi][ni][3]);
            *reinterpret_cast<float2*>(out + (size_t)r0 * OUT_F + c) = v0;
            *reinterpret_cast<float2*>(out + (size_t)(r0 + 8) * OUT_F + c) = v1;
        }
    }
}

// ---------------- host ----------------
extern "C" void kernel_launch(void* const* d_in, const int* in_sizes, int n_in,
                              void* d_out, int out_size) {
    const float* x    = (const float*)d_in[0];   // [8192, 4096] fp32
    const float* cent = (const float*)d_in[1];   // [256, 1] fp32
    const int*   idx  = (const int*)d_in[2];     // [4096, 4096] int32
    float* out = (float*)d_out;                  // [8192, 4096] fp32

    void* w16_ptr = nullptr; cudaGetSymbolAddress(&w16_ptr, g_w16);
    void* x16_ptr = nullptr; cudaGetSymbolAddress(&x16_ptr, g_x16);

    prep_kernel<<<(unsigned)(NB_W + NB_X), 256>>>(cent, idx, x,
                                                  (__half*)w16_ptr, (__half*)x16_ptr);

    cudaFuncSetAttribute(gemm_f16, cudaFuncAttributeMaxDynamicSharedMemorySize, SMEM_BYTES);
    int grid = (MROWS / BM) * (OUT_F / BN);   // 64 * 32 = 2048
    gemm_f16<<<grid, 256, SMEM_BYTES>>>((const __half*)x16_ptr, (const __half*)w16_ptr, out);
}

// round 13
// speedup vs baseline: 1.4183x; 1.1454x over previous
#include <cuda_runtime.h>
#include <cuda.h>
#include <cuda_fp16.h>
#include <cstdint>

#define IN_F   4096
#define OUT_F  4096
#define MROWS  8192          // B*S = 4*2048

#define BM 128
#define BN 128
#define BK 64                // halves per k-tile (128 B rows)
#define STAGES 3
#define KTILES (IN_F / BK)   // 64
#define TILE_BYTES (BM * 128)                      // 16384 per matrix per stage
#define STAGE_BYTES (2 * TILE_BYTES)               // 32768 (A + B)
#define SMEM_HDR 1024
#define SMEM_BYTES (SMEM_HDR + STAGES * STAGE_BYTES)   // 99328

#define MB_FULL(s)  ((s) * 16)
#define MB_EMPTY(s) ((s) * 16 + 8)

// ---------------- scratch (no runtime allocation allowed) -------------------
__device__ __align__(1024) __half g_w16[(size_t)OUT_F * IN_F];   // 32 MB
__device__ __align__(1024) __half g_x16[(size_t)MROWS * IN_F];   // 64 MB

// ---------------- helpers ----------------
__device__ __forceinline__ uint32_t s2u(const void* p) {
    uint32_t a;
    asm("{ .reg .u64 t; cvta.to.shared.u64 t, %1; cvt.u32.u64 %0, t; }" : "=r"(a) : "l"(p));
    return a;
}
__device__ __forceinline__ void mbar_init(uint32_t m, uint32_t cnt) {
    asm volatile("mbarrier.init.shared.b64 [%0], %1;" :: "r"(m), "r"(cnt) : "memory");
}
__device__ __forceinline__ void mbar_arrive(uint32_t m) {
    asm volatile("{ .reg .b64 t; mbarrier.arrive.shared.b64 t, [%0]; }" :: "r"(m) : "memory");
}
__device__ __forceinline__ void mbar_expect_tx(uint32_t m, uint32_t bytes) {
    asm volatile("mbarrier.arrive.expect_tx.shared.b64 _, [%0], %1;" :: "r"(m), "r"(bytes) : "memory");
}
__device__ __forceinline__ void mbar_wait(uint32_t m, uint32_t parity) {
    asm volatile(
        "{\n\t.reg .pred P;\n\t"
        "WL_%=:\n\t"
        "mbarrier.try_wait.parity.acquire.cta.shared::cta.b64 P, [%0], %1, 0x989680;\n\t"
        "@P bra.uni WD_%=;\n\t"
        "bra.uni WL_%=;\n\t"
        "WD_%=:\n\t}"
        :: "r"(m), "r"(parity) : "memory");
}
__device__ __forceinline__ void tma_load_2d(uint32_t dst, const CUtensorMap* map,
                                            int cx, int cy, uint32_t mbar) {
    asm volatile(
        "cp.async.bulk.tensor.2d.shared::cta.global.tile.mbarrier::complete_tx::bytes "
        "[%0], [%1, {%2, %3}], [%4];"
        :: "r"(dst), "l"(map), "r"(cx), "r"(cy), "r"(mbar) : "memory");
}
__device__ __forceinline__ void ldsm_x4(uint32_t* r, uint32_t addr) {
    asm volatile("ldmatrix.sync.aligned.m8n8.x4.shared.b16 {%0,%1,%2,%3}, [%4];"
                 : "=r"(r[0]), "=r"(r[1]), "=r"(r[2]), "=r"(r[3]) : "r"(addr));
}
__device__ __forceinline__ void mma_f16(float* d, const uint32_t* a, const uint32_t* b) {
    asm volatile(
        "mma.sync.aligned.m16n8k16.row.col.f32.f16.f16.f32 "
        "{%0,%1,%2,%3}, {%4,%5,%6,%7}, {%8,%9}, {%0,%1,%2,%3};"
        : "+f"(d[0]), "+f"(d[1]), "+f"(d[2]), "+f"(d[3])
        : "r"(a[0]), "r"(a[1]), "r"(a[2]), "r"(a[3]), "r"(b[0]), "r"(b[1]));
}

// ------------- kernel 1: fused preprocessing (wdeq || xcvt) -----------------
#define NB_W ((size_t)OUT_F * IN_F / 2048)   // 8192
#define NB_X ((size_t)MROWS * IN_F / 2048)   // 16384

__global__ void __launch_bounds__(256) prep_kernel(const float* __restrict__ cent,
                                                   const int* __restrict__ idx,
                                                   const float* __restrict__ x,
                                                   __half* __restrict__ w,
                                                   __half* __restrict__ y) {
    int t = threadIdx.x;
    if (blockIdx.x < NB_W) {
        __shared__ __half c[256];
        c[t] = __float2half_rn(cent[t]);
        __syncthreads();
        size_t i = ((size_t)blockIdx.x * 256 + t) * 8;
        int4 v0 = *reinterpret_cast<const int4*>(idx + i);
        int4 v1 = *reinterpret_cast<const int4*>(idx + i + 4);
        __half h[8];
        h[0] = c[v0.x]; h[1] = c[v0.y]; h[2] = c[v0.z]; h[3] = c[v0.w];
        h[4] = c[v1.x]; h[5] = c[v1.y]; h[6] = c[v1.z]; h[7] = c[v1.w];
        *reinterpret_cast<uint4*>(w + i) = *reinterpret_cast<uint4*>(h);
    } else {
        size_t i = ((size_t)(blockIdx.x - NB_W) * 256 + t) * 8;
        float4 v0 = *reinterpret_cast<const float4*>(x + i);
        float4 v1 = *reinterpret_cast<const float4*>(x + i + 4);
        __half h[8];
        h[0] = __float2half_rn(v0.x); h[1] = __float2half_rn(v0.y);
        h[2] = __float2half_rn(v0.z); h[3] = __float2half_rn(v0.w);
        h[4] = __float2half_rn(v1.x); h[5] = __float2half_rn(v1.y);
        h[6] = __float2half_rn(v1.z); h[7] = __float2half_rn(v1.w);
        *reinterpret_cast<uint4*>(y + i) = *reinterpret_cast<uint4*>(h);
    }
}

// ---------------- kernel 2: fp16 mma GEMM, TMA + mbarrier pipeline ----------
// out[m,n] = sum_k X[m,k] * W[n,k]
// smem tile layout: 128 rows x 128 B (64 halves), SW128 XOR swizzle (TMA-written)
__global__ void __launch_bounds__(256, 2)
gemm_f16(const __grid_constant__ CUtensorMap tma_a,
         const __grid_constant__ CUtensorMap tma_b,
         float* __restrict__ out) {
    extern __shared__ char smem_raw[];
    const uint32_t sb = s2u(smem_raw);                 // mbarriers at sb
    const uint32_t data0 = sb + SMEM_HDR;

    const int tid = threadIdx.x;
    const int wid = tid >> 5, lane = tid & 31;
    const int warp_m = wid >> 2;      // 0..1 -> 64 rows
    const int warp_n = wid & 3;       // 0..3 -> 32 cols

    if (tid == 0) {
        #pragma unroll
        for (int s = 0; s < STAGES; s++) {
            mbar_init(sb + MB_FULL(s), 1);     // producer expect_tx arrival
            mbar_init(sb + MB_EMPTY(s), 256);  // all consumers arrive
        }
    }
    __syncthreads();

    // grid swizzle: 8 M-tiles per supertile column (L2 reuse of W)
    const int NT = OUT_F / BN;        // 32
    const int GM = 8;
    int bid = blockIdx.x;
    int grp = bid / (GM * NT);
    int inb = bid % (GM * NT);
    int m_tile = grp * GM + (inb % GM);
    int n_tile = inb / GM;
    const int m_base = m_tile * BM;
    const int n_base = n_tile * BN;

    // ldmatrix lane addressing (SW128 swizzled, 128 B rows)
    const int l7 = lane & 7;
    const int a_row = warp_m * 64 + l7 + ((lane >> 3) & 1) * 8;
    const int a_kbl = ((lane >> 4) & 1) * 16;            // byte sel within row
    const int b_row = warp_n * 32 + l7 + ((lane >> 4) & 1) * 8;
    const int b_kbl = ((lane >> 3) & 1) * 16;
    const uint32_t a_rowoff = (uint32_t)(a_row * 128);
    const uint32_t b_rowoff = (uint32_t)(b_row * 128);
    const uint32_t a_t = (uint32_t)a_kbl ^ (uint32_t)((a_row & 7) * 16);
    const uint32_t b_t = (uint32_t)b_kbl ^ (uint32_t)((b_row & 7) * 16);

    float acc[4][4][4];
    #pragma unroll
    for (int mi = 0; mi < 4; mi++)
        #pragma unroll
        for (int ni = 0; ni < 4; ni++)
            #pragma unroll
            for (int e = 0; e < 4; e++) acc[mi][ni][e] = 0.f;

    auto produce = [&](int kt, int s) {      // tid 0 only
        uint32_t a_dst = data0 + (uint32_t)(s * STAGE_BYTES);
        uint32_t b_dst = a_dst + TILE_BYTES;
        mbar_expect_tx(sb + MB_FULL(s), STAGE_BYTES);
        tma_load_2d(a_dst, &tma_a, kt * BK, m_base, sb + MB_FULL(s));
        tma_load_2d(b_dst, &tma_b, kt * BK, n_base, sb + MB_FULL(s));
    };

    // ---- prologue: fill stages 0 and 1 (fresh empty barriers: parity 1 passes)
    if (tid == 0) {
        mbar_wait(sb + MB_EMPTY(0), 1);
        produce(0, 0);
        mbar_wait(sb + MB_EMPTY(1), 1);
        produce(1, 1);
    }

    int ps = 2, pph = 1;      // producer empty-cursor
    int cs = 0, cph = 0;      // consumer full-cursor

    for (int kt = 0; kt < KTILES; kt++) {
        if (tid == 0 && kt + 2 < KTILES) {
            mbar_wait(sb + MB_EMPTY(ps), pph);
            produce(kt + 2, ps);
        }
        if (kt + 2 < KTILES) {
            if (++ps == STAGES) { ps = 0; pph ^= 1; }
        }

        mbar_wait(sb + MB_FULL(cs), cph);

        const uint32_t a_stage = data0 + (uint32_t)(cs * STAGE_BYTES);
        const uint32_t b_stage = a_stage + TILE_BYTES;
        #pragma unroll
        for (int k0 = 0; k0 < 4; k0++) {       // 4 k-steps of 16 halves (32 B)
            const uint32_t KB = (uint32_t)(k0 * 32);
            uint32_t a[4][4], b[2][4];
            #pragma unroll
            for (int mi = 0; mi < 4; mi++)
                ldsm_x4(a[mi], a_stage + a_rowoff + (uint32_t)(mi * 16 * 128) + (KB ^ a_t));
            ldsm_x4(b[0], b_stage + b_rowoff + (KB ^ b_t));
            ldsm_x4(b[1], b_stage + b_rowoff + (uint32_t)(16 * 128) + (KB ^ b_t));
            #pragma unroll
            for (int mi = 0; mi < 4; mi++) {
                mma_f16(acc[mi][0], a[mi], &b[0][0]);
                mma_f16(acc[mi][1], a[mi], &b[0][2]);
                mma_f16(acc[mi][2], a[mi], &b[1][0]);
                mma_f16(acc[mi][3], a[mi], &b[1][2]);
            }
        }

        mbar_arrive(sb + MB_EMPTY(cs));
        if (++cs == STAGES) { cs = 0; cph ^= 1; }
    }

    // epilogue: direct STG.64
    #pragma unroll
    for (int mi = 0; mi < 4; mi++) {
        int r0 = m_base + warp_m * 64 + mi * 16 + (lane >> 2);
        #pragma unroll
        for (int ni = 0; ni < 4; ni++) {
            int c = n_base + warp_n * 32 + ni * 8 + 2 * (lane & 3);
            float2 v0 = make_float2(acc[mi][ni][0], acc[mi][ni][1]);
            float2 v1 = make_float2(acc[mi][ni][2], acc[mi][ni][3]);
            *reinterpret_cast<float2*>(out + (size_t)r0 * OUT_F + c) = v0;
            *reinterpret_cast<float2*>(out + (size_t)(r0 + 8) * OUT_F + c) = v1;
        }
    }
}

// ---------------- host ----------------
typedef CUresult (*EncodeFn)(CUtensorMap*, CUtensorMapDataType, cuuint32_t, void*,
                             const cuuint64_t*, const cuuint64_t*, const cuuint32_t*,
                             const cuuint32_t*, CUtensorMapInterleave, CUtensorMapSwizzle,
                             CUtensorMapL2promotion, CUtensorMapFloatOOBfill);

extern "C" void kernel_launch(void* const* d_in, const int* in_sizes, int n_in,
                              void* d_out, int out_size) {
    const float* x    = (const float*)d_in[0];   // [8192, 4096] fp32
    const float* cent = (const float*)d_in[1];   // [256, 1] fp32
    const int*   idx  = (const int*)d_in[2];     // [4096, 4096] int32
    float* out = (float*)d_out;                  // [8192, 4096] fp32

    void* w16_ptr = nullptr; cudaGetSymbolAddress(&w16_ptr, g_w16);
    void* x16_ptr = nullptr; cudaGetSymbolAddress(&x16_ptr, g_x16);

    prep_kernel<<<(unsigned)(NB_W + NB_X), 256>>>(cent, idx, x,
                                                  (__half*)w16_ptr, (__half*)x16_ptr);

    // TMA descriptors
    void* fn = nullptr;
    cudaDriverEntryPointQueryResult qr;
    cudaGetDriverEntryPointByVersion("cuTensorMapEncodeTiled", &fn, 12000,
                                     cudaEnableDefault, &qr);
    EncodeFn enc = (EncodeFn)fn;

    CUtensorMap ta, tb;
    {
        cuuint64_t dims[2]    = {IN_F, MROWS};
        cuuint64_t strides[1] = {(cuuint64_t)IN_F * 2};
        cuuint32_t box[2]     = {BK, BM};        // 64 halves = 128 B rows, 128 rows
        cuuint32_t es[2]      = {1, 1};
        enc(&ta, CU_TENSOR_MAP_DATA_TYPE_UINT16, 2, x16_ptr, dims, strides, box, es,
            CU_TENSOR_MAP_INTERLEAVE_NONE, CU_TENSOR_MAP_SWIZZLE_128B,
            CU_TENSOR_MAP_L2_PROMOTION_L2_128B, CU_TENSOR_MAP_FLOAT_OOB_FILL_NONE);
    }
    {
        cuuint64_t dims[2]    = {IN_F, OUT_F};
        cuuint64_t strides[1] = {(cuuint64_t)IN_F * 2};
        cuuint32_t box[2]     = {BK, BN};
        cuuint32_t es[2]      = {1, 1};
        enc(&tb, CU_TENSOR_MAP_DATA_TYPE_UINT16, 2, w16_ptr, dims, strides, box, es,
            CU_TENSOR_MAP_INTERLEAVE_NONE, CU_TENSOR_MAP_SWIZZLE_128B,
            CU_TENSOR_MAP_L2_PROMOTION_L2_128B, CU_TENSOR_MAP_FLOAT_OOB_FILL_NONE);
    }

    cudaFuncSetAttribute(gemm_f16, cudaFuncAttributeMaxDynamicSharedMemorySize, SMEM_BYTES);
    int grid = (MROWS / BM) * (OUT_F / BN);   // 64 * 32 = 2048
    gemm_f16<<<grid, 256, SMEM_BYTES>>>(ta, tb, out);
}